// round 3
// baseline (speedup 1.0000x reference)
#include <cuda_runtime.h>
#include <math.h>

#define DIM    64
#define NCODES 1024
#define NROWS  65536          // 16 * 64 * 64
#define HW     4096           // 64 * 64
#define QELEMS 4194304        // 16 * 64 * 64 * 64
#define FULL_OUT 71368706     // 1 + QELEMS + 1 + NROWS*NCODES + NROWS

__device__ float  g_b[NCODES];
__device__ int    g_hist[NCODES];
__device__ double g_loss;

// ---- packed f32x2 helpers ---------------------------------------------------
__device__ __forceinline__ void fma2(unsigned long long& d,
                                     unsigned long long a, unsigned long long b) {
    asm("fma.rn.f32x2 %0, %1, %2, %0;" : "+l"(d) : "l"(a), "l"(b));
}
__device__ __forceinline__ unsigned long long pack2(float x, float y) {
    unsigned long long r;
    asm("mov.b64 %0, {%1, %2};" : "=l"(r) : "f"(x), "f"(y));
    return r;
}
__device__ __forceinline__ void unpack2(unsigned long long v, float& lo, float& hi) {
    asm("mov.b64 {%0, %1}, %2;" : "=f"(lo), "=f"(hi) : "l"(v));
}

// ---------------------------------------------------------------------------
// init: zero accumulators, compute b_k = ||e_k||^2 with reference-style
// rounding (round(mul) then round(add), sequential d order).
// ---------------------------------------------------------------------------
__global__ void init_kernel(const float* __restrict__ emb) {
    int t = threadIdx.x;                 // 1024 threads
    g_hist[t] = 0;
    if (t == 0) g_loss = 0.0;
    const float* e = emb + t * DIM;
    float s = 0.f;
#pragma unroll
    for (int d = 0; d < DIM; ++d) s = __fadd_rn(s, __fmul_rn(e[d], e[d]));
    g_b[t] = s;
}

// ---------------------------------------------------------------------------
// fused: argmin (f32x2-packed GEMM) + hist + loss + indices + quantized +
// one-hot encodings, all per 128-row block.
// Thread tile: 8 rows x 4 codes. tr = tid&15 (rows tr*8..+7),
// tc = tid>>4 (codes tc*4..+3 within each 64-code chunk).
// Per-(row,code) dot chain is bitwise identical to the scalar sequential-d
// FMA chain (f32x2 = two independent fp32 FMAs).
// ---------------------------------------------------------------------------
__global__ __launch_bounds__(256, 2) void fused_kernel(
    const float* __restrict__ xin, const float* __restrict__ emb,
    float* __restrict__ oq, float* __restrict__ oenc, float* __restrict__ oidx)
{
    __shared__ __align__(16) float Xs[DIM * 128];   // [d][row]  32 KB
    __shared__ __align__(16) float Es[64 * DIM];    // [code][d] 16 KB (reused)

    int tid = threadIdx.x;
    int R0  = (tid & 15) * 8;         // first of 8 rows
    int C0  = (tid >> 4) * 4;         // first of 4 codes (within chunk)
    int n0  = blockIdx.x * 128;
    int img = n0 >> 12;               // blocks never straddle images
    int hw0 = n0 & 4095;
    const float* gbase = xin + (size_t)img * (DIM * HW) + hw0;

    // Stage X tile: NCHW -> smem[d][row], fully coalesced
    for (int i = tid; i < DIM * 128; i += 256) {
        int d = i >> 7;
        int r = i & 127;
        Xs[i] = gbase[d * HW + r];
    }
    __syncthreads();

    // a_r = ||x_row||^2, sequential d order, rounded mul + rounded add
    float a[8];
#pragma unroll
    for (int r = 0; r < 8; ++r) {
        float s = 0.f;
#pragma unroll
        for (int d = 0; d < DIM; ++d) {
            float v = Xs[d * 128 + R0 + r];
            s = __fadd_rn(s, __fmul_rn(v, v));
        }
        a[r] = s;
    }

    float best[8];
    int   bidx[8];
#pragma unroll
    for (int r = 0; r < 8; ++r) { best[r] = __int_as_float(0x7f800000); bidx[r] = 0; }

    for (int chunk = 0; chunk < 16; ++chunk) {
        __syncthreads();                         // prior-chunk Es reads done
        const float* ec = emb + chunk * (64 * DIM);
        for (int i = tid; i < 64 * DIM; i += 256) Es[i] = ec[i];
        __syncthreads();

        unsigned long long acc[4][4];            // [row-pair][code], packed f32x2
#pragma unroll
        for (int p = 0; p < 4; ++p)
#pragma unroll
            for (int j = 0; j < 4; ++j) acc[p][j] = 0ull;

#pragma unroll 4
        for (int dk = 0; dk < DIM; dk += 4) {
            float4 e4[4];
#pragma unroll
            for (int j = 0; j < 4; ++j)
                e4[j] = *(const float4*)&Es[(C0 + j) * DIM + dk];
#pragma unroll
            for (int t = 0; t < 4; ++t) {
                float4 x0 = *(const float4*)&Xs[(dk + t) * 128 + R0];
                float4 x1 = *(const float4*)&Xs[(dk + t) * 128 + R0 + 4];
                unsigned long long xp0 = pack2(x0.x, x0.y);
                unsigned long long xp1 = pack2(x0.z, x0.w);
                unsigned long long xp2 = pack2(x1.x, x1.y);
                unsigned long long xp3 = pack2(x1.z, x1.w);
#pragma unroll
                for (int j = 0; j < 4; ++j) {
                    float ev = ((const float*)&e4[j])[t];
                    unsigned long long ee = pack2(ev, ev);
                    fma2(acc[0][j], xp0, ee);
                    fma2(acc[1][j], xp1, ee);
                    fma2(acc[2][j], xp2, ee);
                    fma2(acc[3][j], xp3, ee);
                }
            }
        }

        // score: d = round(round(a + b) - 2*m), strict < keeps lowest index
#pragma unroll
        for (int j = 0; j < 4; ++j) {
            int code = chunk * 64 + C0 + j;      // strictly ascending per thread
            float bb = g_b[code];
#pragma unroll
            for (int p = 0; p < 4; ++p) {
                float m0, m1;
                unpack2(acc[p][j], m0, m1);
                int r0 = 2 * p, r1 = 2 * p + 1;
                float s0 = __fadd_rn(__fadd_rn(a[r0], bb), -2.0f * m0);
                float s1 = __fadd_rn(__fadd_rn(a[r1], bb), -2.0f * m1);
                if (s0 < best[r0]) { best[r0] = s0; bidx[r0] = code; }
                if (s1 < best[r1]) { best[r1] = s1; bidx[r1] = code; }
            }
        }
    }

    // Cross-thread argmin: pack (score_bits << 32) | idx, atomicMin.
    // Distances ~64 >> 0 so fp32 bits are order-preserving; equal scores ->
    // smaller index wins (== jnp.argmin first-occurrence).
    __syncthreads();
    unsigned long long* keys = (unsigned long long*)Es;   // 1 KB of Es
    int* sidx = (int*)&Es[512];                           // next 512 B of Es
    if (tid < 128) keys[tid] = 0xFFFFFFFFFFFFFFFFull;
    __syncthreads();
#pragma unroll
    for (int r = 0; r < 8; ++r) {
        unsigned long long key =
            ((unsigned long long)__float_as_uint(best[r]) << 32) | (unsigned)bidx[r];
        atomicMin(&keys[R0 + r], key);
    }
    __syncthreads();

    double lsum = 0.0;
    if (tid < 128) {
        int idx = (int)(keys[tid] & 0xFFFFFFFFull);
        sidx[tid] = idx;
        atomicAdd(&g_hist[idx], 1);
        if (oidx) oidx[n0 + tid] = (float)idx;
        const float* e = emb + idx * DIM;
        float s = 0.f;
#pragma unroll
        for (int d = 0; d < DIM; ++d) {
            float dif = e[d] - Xs[d * 128 + tid];
            s = __fmaf_rn(dif, dif, s);
        }
        lsum = (double)s;
    }
#pragma unroll
    for (int off = 16; off; off >>= 1)
        lsum += __shfl_down_sync(0xffffffffu, lsum, off);
    if (tid < 128 && (tid & 31) == 0) atomicAdd(&g_loss, lsum);
    __syncthreads();

    // quantized_st, NCHW: per channel c, 128 consecutive floats (coalesced)
    for (int i = tid; i < DIM * 128; i += 256) {
        int c = i >> 7, row = i & 127;
        oq[(size_t)img * (DIM * HW) + c * HW + hw0 + row] = emb[sidx[row] * DIM + c];
    }

    // one-hot encodings: 128 rows x 512 float2 (base only 8B-aligned)
    if (oenc) {
        float2* enc2 = (float2*)oenc;
        for (int i = tid; i < 128 * 512; i += 256) {
            int row = i >> 9, jj = i & 511;
            int idx = sidx[row];
            float2 z = make_float2(0.f, 0.f);
            if ((idx >> 1) == jj) ((float*)&z)[idx & 1] = 1.0f;
            enc2[(size_t)(n0 + row) * 512 + jj] = z;
        }
    }
}

// ---------------------------------------------------------------------------
// finalize: loss scalar + perplexity from histogram
// ---------------------------------------------------------------------------
__global__ void finalize_kernel(float* __restrict__ oloss, float* __restrict__ operp) {
    int t = threadIdx.x;                         // 1024 threads
    double p = (double)g_hist[t] / 65536.0;
    double h = -p * log(p + 1e-10);
    __shared__ double sh[32];
#pragma unroll
    for (int off = 16; off; off >>= 1) h += __shfl_down_sync(0xffffffffu, h, off);
    if ((t & 31) == 0) sh[t >> 5] = h;
    __syncthreads();
    if (t < 32) {
        double v = sh[t];
#pragma unroll
        for (int off = 16; off; off >>= 1) v += __shfl_down_sync(0xffffffffu, v, off);
        if (t == 0) {
            operp[0] = (float)exp(v);
            oloss[0] = (float)(1.25 * (g_loss / (double)QELEMS));
        }
    }
}

// ---------------------------------------------------------------------------
extern "C" void kernel_launch(void* const* d_in, const int* in_sizes, int n_in,
                              void* d_out, int out_size) {
    const float* xin = (const float*)d_in[0];
    const float* emb = (const float*)d_in[1];
    if (n_in >= 2 && in_sizes[0] == NCODES * DIM && in_sizes[1] == QELEMS) {
        xin = (const float*)d_in[1];
        emb = (const float*)d_in[0];
    }
    float* out  = (float*)d_out;
    bool   full = (out_size >= FULL_OUT);
    float* o_q   = full ? out + 1 : out;
    float* o_enc = full ? out + (size_t)QELEMS + 2 : nullptr;
    float* o_idx = full ? out + (size_t)QELEMS + 2 + (size_t)NROWS * NCODES : nullptr;

    init_kernel<<<1, 1024>>>(emb);
    fused_kernel<<<512, 256>>>(xin, emb, o_q, o_enc, o_idx);
    if (full) finalize_kernel<<<1, 1024>>>(out, out + QELEMS + 1);
}

// round 4
// speedup vs baseline: 1.4000x; 1.4000x over previous
#include <cuda_runtime.h>
#include <math.h>

#define DIM    64
#define NCODES 1024
#define NROWS  65536          // 16 * 64 * 64
#define HW     4096           // 64 * 64
#define QELEMS 4194304        // 16 * 64 * 64 * 64
#define FULL_OUT 71368706     // 1 + QELEMS + 1 + NROWS*NCODES + NROWS

__device__ float  g_b[NCODES];
__device__ int    g_hist[NCODES];
__device__ double g_loss;

// ---------------------------------------------------------------------------
// init: zero accumulators, compute b_k = ||e_k||^2 with reference-style
// rounding (round(mul) then round(add), sequential d order).
// 8 blocks x 128 threads: one code per thread, float4 loads (MLP=16).
// ---------------------------------------------------------------------------
__global__ void init_kernel(const float* __restrict__ emb) {
    int t = blockIdx.x * 128 + threadIdx.x;      // 0..1023
    g_hist[t] = 0;
    if (t == 0) g_loss = 0.0;
    const float4* e4 = (const float4*)(emb + t * DIM);
    float4 v[16];
#pragma unroll
    for (int i = 0; i < 16; ++i) v[i] = e4[i];   // batched loads, high MLP
    float s = 0.f;
#pragma unroll
    for (int i = 0; i < 16; ++i) {               // sequential-d rounding chain
        s = __fadd_rn(s, __fmul_rn(v[i].x, v[i].x));
        s = __fadd_rn(s, __fmul_rn(v[i].y, v[i].y));
        s = __fadd_rn(s, __fmul_rn(v[i].z, v[i].z));
        s = __fadd_rn(s, __fmul_rn(v[i].w, v[i].w));
    }
    g_b[t] = s;
}

// ---------------------------------------------------------------------------
// fused: argmin (scalar FFMA GEMM, R2 mainloop verbatim) + hist + loss +
// indices + quantized + one-hot encodings, per 128-row block.
// Thread tile: 4 rows x 8 codes (tr=tid&31, tc=tid>>5).
// ---------------------------------------------------------------------------
__global__ __launch_bounds__(256, 2) void fused_kernel(
    const float* __restrict__ xin, const float* __restrict__ emb,
    float* __restrict__ oq, float* __restrict__ oenc, float* __restrict__ oidx)
{
    __shared__ __align__(16) float Xs[DIM * 128];   // [d][row]  32 KB
    __shared__ __align__(16) float Es[64 * DIM];    // [code][d] 16 KB (reused)

    int tid = threadIdx.x;
    int tr  = tid & 31;               // rows tr*4 .. tr*4+3
    int tc  = tid >> 5;               // codes tc*8 .. tc*8+7 per chunk
    int n0  = blockIdx.x * 128;
    int img = n0 >> 12;               // blocks never straddle images
    int hw0 = n0 & 4095;
    const float* gbase = xin + (size_t)img * (DIM * HW) + hw0;

    // Stage X tile: NCHW -> smem[d][row], fully coalesced
    for (int i = tid; i < DIM * 128; i += 256) {
        int d = i >> 7;
        int r = i & 127;
        Xs[i] = gbase[d * HW + r];
    }
    __syncthreads();

    // a_r = ||x_row||^2, sequential d order, rounded mul + rounded add
    float a[4];
#pragma unroll
    for (int r = 0; r < 4; ++r) {
        int row = tr * 4 + r;
        float s = 0.f;
#pragma unroll
        for (int d = 0; d < DIM; ++d) {
            float v = Xs[d * 128 + row];
            s = __fadd_rn(s, __fmul_rn(v, v));
        }
        a[r] = s;
    }

    float best[4];
    int   bidx[4];
#pragma unroll
    for (int r = 0; r < 4; ++r) { best[r] = __int_as_float(0x7f800000); bidx[r] = 0; }

    for (int chunk = 0; chunk < 16; ++chunk) {
        __syncthreads();                         // prior-chunk Es reads done
        const float* ec = emb + chunk * (64 * DIM);
        for (int i = tid; i < 64 * DIM; i += 256) Es[i] = ec[i];
        __syncthreads();

        float acc[4][8];
#pragma unroll
        for (int r = 0; r < 4; ++r)
#pragma unroll
            for (int j = 0; j < 8; ++j) acc[r][j] = 0.f;

        // m = x . e  via sequential-d FMA chain (12x LDS.128 per 128 FMA)
#pragma unroll 4
        for (int dk = 0; dk < DIM; dk += 4) {
            float4 e4[8];
#pragma unroll
            for (int j = 0; j < 8; ++j)
                e4[j] = *(const float4*)&Es[(tc * 8 + j) * DIM + dk];
#pragma unroll
            for (int t = 0; t < 4; ++t) {
                float4 xv = *(const float4*)&Xs[(dk + t) * 128 + tr * 4];
#pragma unroll
                for (int j = 0; j < 8; ++j) {
                    float ev = ((const float*)&e4[j])[t];
                    acc[0][j] = __fmaf_rn(xv.x, ev, acc[0][j]);
                    acc[1][j] = __fmaf_rn(xv.y, ev, acc[1][j]);
                    acc[2][j] = __fmaf_rn(xv.z, ev, acc[2][j]);
                    acc[3][j] = __fmaf_rn(xv.w, ev, acc[3][j]);
                }
            }
        }

        // score with the reference's exact rounding chain:
        // d = round(round(a + b) - 2*m)      (2*m is exact)
#pragma unroll
        for (int j = 0; j < 8; ++j) {
            int code = chunk * 64 + tc * 8 + j;   // strictly ascending per thread
            float bb = g_b[code];
#pragma unroll
            for (int r = 0; r < 4; ++r) {
                float s = __fadd_rn(__fadd_rn(a[r], bb), -2.0f * acc[r][j]);
                if (s < best[r]) { best[r] = s; bidx[r] = code; }
            }
        }
    }

    // Cross-thread argmin: pack (score_bits << 32) | idx, atomicMin.
    // Distances >> 0 so fp32 bits are order-preserving; equal scores ->
    // smaller index wins (== jnp.argmin first-occurrence).
    __syncthreads();
    unsigned long long* keys = (unsigned long long*)Es;   // 1 KB of Es
    int* sidx = (int*)&Es[512];                           // next 512 B of Es
    if (tid < 128) keys[tid] = 0xFFFFFFFFFFFFFFFFull;
    __syncthreads();
#pragma unroll
    for (int r = 0; r < 4; ++r) {
        unsigned long long key =
            ((unsigned long long)__float_as_uint(best[r]) << 32) | (unsigned)bidx[r];
        atomicMin(&keys[tr * 4 + r], key);
    }
    __syncthreads();

    double lsum = 0.0;
    if (tid < 128) {
        int idx = (int)(keys[tid] & 0xFFFFFFFFull);
        sidx[tid] = idx;
        atomicAdd(&g_hist[idx], 1);
        if (oidx) oidx[n0 + tid] = (float)idx;
        const float* e = emb + idx * DIM;
        float s = 0.f;
#pragma unroll
        for (int d = 0; d < DIM; ++d) {
            float dif = e[d] - Xs[d * 128 + tid];
            s = __fmaf_rn(dif, dif, s);
        }
        lsum = (double)s;
    }
#pragma unroll
    for (int off = 16; off; off >>= 1)
        lsum += __shfl_down_sync(0xffffffffu, lsum, off);
    if (tid < 128 && (tid & 31) == 0) atomicAdd(&g_loss, lsum);
    __syncthreads();

    // quantized_st, NCHW: per channel c, 128 consecutive floats (coalesced)
    for (int i = tid; i < DIM * 128; i += 256) {
        int c = i >> 7, row = i & 127;
        oq[(size_t)img * (DIM * HW) + c * HW + hw0 + row] = emb[sidx[row] * DIM + c];
    }

    // one-hot encodings: 128 rows x 512 float2 (base only 8B-aligned)
    if (oenc) {
        float2* enc2 = (float2*)oenc;
        for (int i = tid; i < 128 * 512; i += 256) {
            int row = i >> 9, jj = i & 511;
            int idx = sidx[row];
            float2 z = make_float2(0.f, 0.f);
            if ((idx >> 1) == jj) ((float*)&z)[idx & 1] = 1.0f;
            enc2[(size_t)(n0 + row) * 512 + jj] = z;
        }
    }
}

// ---------------------------------------------------------------------------
// finalize: loss scalar + perplexity from histogram
// ---------------------------------------------------------------------------
__global__ void finalize_kernel(float* __restrict__ oloss, float* __restrict__ operp) {
    int t = threadIdx.x;                         // 1024 threads
    double p = (double)g_hist[t] / 65536.0;
    double h = -p * log(p + 1e-10);
    __shared__ double sh[32];
#pragma unroll
    for (int off = 16; off; off >>= 1) h += __shfl_down_sync(0xffffffffu, h, off);
    if ((t & 31) == 0) sh[t >> 5] = h;
    __syncthreads();
    if (t < 32) {
        double v = sh[t];
#pragma unroll
        for (int off = 16; off; off >>= 1) v += __shfl_down_sync(0xffffffffu, v, off);
        if (t == 0) {
            operp[0] = (float)exp(v);
            oloss[0] = (float)(1.25 * (g_loss / (double)QELEMS));
        }
    }
}

// ---------------------------------------------------------------------------
extern "C" void kernel_launch(void* const* d_in, const int* in_sizes, int n_in,
                              void* d_out, int out_size) {
    const float* xin = (const float*)d_in[0];
    const float* emb = (const float*)d_in[1];
    if (n_in >= 2 && in_sizes[0] == NCODES * DIM && in_sizes[1] == QELEMS) {
        xin = (const float*)d_in[1];
        emb = (const float*)d_in[0];
    }
    float* out  = (float*)d_out;
    bool   full = (out_size >= FULL_OUT);
    float* o_q   = full ? out + 1 : out;
    float* o_enc = full ? out + (size_t)QELEMS + 2 : nullptr;
    float* o_idx = full ? out + (size_t)QELEMS + 2 + (size_t)NROWS * NCODES : nullptr;

    init_kernel<<<8, 128>>>(emb);
    fused_kernel<<<512, 256>>>(xin, emb, o_q, o_enc, o_idx);
    if (full) finalize_kernel<<<1, 1024>>>(out, out + QELEMS + 1);
}

// round 5
// speedup vs baseline: 1.4045x; 1.0032x over previous
#include <cuda_runtime.h>
#include <math.h>

#define DIM    64
#define NCODES 1024
#define NROWS  65536          // 16 * 64 * 64
#define HW     4096           // 64 * 64
#define QELEMS 4194304        // 16 * 64 * 64 * 64
#define FULL_OUT 71368706     // 1 + QELEMS + 1 + NROWS*NCODES + NROWS

__device__ float  g_b[NCODES];
__device__ int    g_hist[NCODES];
__device__ double g_loss;

// ---------------------------------------------------------------------------
// init: zero accumulators, compute b_k = ||e_k||^2 with reference-style
// rounding (round(mul) then round(add), sequential d order).
// 8 blocks x 128 threads: one code per thread, float4 loads (MLP=16).
// ---------------------------------------------------------------------------
__global__ void init_kernel(const float* __restrict__ emb) {
    int t = blockIdx.x * 128 + threadIdx.x;      // 0..1023
    g_hist[t] = 0;
    if (t == 0) g_loss = 0.0;
    const float4* e4 = (const float4*)(emb + t * DIM);
    float4 v[16];
#pragma unroll
    for (int i = 0; i < 16; ++i) v[i] = e4[i];   // batched loads, high MLP
    float s = 0.f;
#pragma unroll
    for (int i = 0; i < 16; ++i) {               // sequential-d rounding chain
        s = __fadd_rn(s, __fmul_rn(v[i].x, v[i].x));
        s = __fadd_rn(s, __fmul_rn(v[i].y, v[i].y));
        s = __fadd_rn(s, __fmul_rn(v[i].z, v[i].z));
        s = __fadd_rn(s, __fmul_rn(v[i].w, v[i].w));
    }
    g_b[t] = s;
}

// ---------------------------------------------------------------------------
// fused: argmin (scalar FFMA GEMM, R2 mainloop verbatim) + hist + loss +
// indices + quantized + one-hot encodings, per 128-row block.
// Thread tile: 4 rows x 8 codes (tr=tid&31, tc=tid>>5).
// ---------------------------------------------------------------------------
__global__ __launch_bounds__(256, 2) void fused_kernel(
    const float* __restrict__ xin, const float* __restrict__ emb,
    float* __restrict__ oq, float* __restrict__ oenc, float* __restrict__ oidx)
{
    __shared__ __align__(16) float Xs[DIM * 128];   // [d][row]  32 KB
    __shared__ __align__(16) float Es[64 * DIM];    // [code][d] 16 KB (reused)

    int tid = threadIdx.x;
    int tr  = tid & 31;               // rows tr*4 .. tr*4+3
    int tc  = tid >> 5;               // codes tc*8 .. tc*8+7 per chunk
    int n0  = blockIdx.x * 128;
    int img = n0 >> 12;               // blocks never straddle images
    int hw0 = n0 & 4095;
    const float* gbase = xin + (size_t)img * (DIM * HW) + hw0;

    // Stage X tile: NCHW -> smem[d][row], fully coalesced
    for (int i = tid; i < DIM * 128; i += 256) {
        int d = i >> 7;
        int r = i & 127;
        Xs[i] = gbase[d * HW + r];
    }
    __syncthreads();

    // a_r = ||x_row||^2, sequential d order, rounded mul + rounded add
    float a[4];
#pragma unroll
    for (int r = 0; r < 4; ++r) {
        int row = tr * 4 + r;
        float s = 0.f;
#pragma unroll
        for (int d = 0; d < DIM; ++d) {
            float v = Xs[d * 128 + row];
            s = __fadd_rn(s, __fmul_rn(v, v));
        }
        a[r] = s;
    }

    float best[4];
    int   bidx[4];
#pragma unroll
    for (int r = 0; r < 4; ++r) { best[r] = __int_as_float(0x7f800000); bidx[r] = 0; }

    for (int chunk = 0; chunk < 16; ++chunk) {
        __syncthreads();                         // prior-chunk Es reads done
        const float* ec = emb + chunk * (64 * DIM);
        for (int i = tid; i < 64 * DIM; i += 256) Es[i] = ec[i];
        __syncthreads();

        float acc[4][8];
#pragma unroll
        for (int r = 0; r < 4; ++r)
#pragma unroll
            for (int j = 0; j < 8; ++j) acc[r][j] = 0.f;

        // m = x . e  via sequential-d FMA chain (12x LDS.128 per 128 FMA)
#pragma unroll 4
        for (int dk = 0; dk < DIM; dk += 4) {
            float4 e4[8];
#pragma unroll
            for (int j = 0; j < 8; ++j)
                e4[j] = *(const float4*)&Es[(tc * 8 + j) * DIM + dk];
#pragma unroll
            for (int t = 0; t < 4; ++t) {
                float4 xv = *(const float4*)&Xs[(dk + t) * 128 + tr * 4];
#pragma unroll
                for (int j = 0; j < 8; ++j) {
                    float ev = ((const float*)&e4[j])[t];
                    acc[0][j] = __fmaf_rn(xv.x, ev, acc[0][j]);
                    acc[1][j] = __fmaf_rn(xv.y, ev, acc[1][j]);
                    acc[2][j] = __fmaf_rn(xv.z, ev, acc[2][j]);
                    acc[3][j] = __fmaf_rn(xv.w, ev, acc[3][j]);
                }
            }
        }

        // score with the reference's exact rounding chain:
        // d = round(round(a + b) - 2*m)      (2*m is exact)
#pragma unroll
        for (int j = 0; j < 8; ++j) {
            int code = chunk * 64 + tc * 8 + j;   // strictly ascending per thread
            float bb = g_b[code];
#pragma unroll
            for (int r = 0; r < 4; ++r) {
                float s = __fadd_rn(__fadd_rn(a[r], bb), -2.0f * acc[r][j]);
                if (s < best[r]) { best[r] = s; bidx[r] = code; }
            }
        }
    }

    // Cross-thread argmin: pack (score_bits << 32) | idx, atomicMin.
    // Distances >> 0 so fp32 bits are order-preserving; equal scores ->
    // smaller index wins (== jnp.argmin first-occurrence).
    __syncthreads();
    unsigned long long* keys = (unsigned long long*)Es;   // 1 KB of Es
    int* sidx = (int*)&Es[512];                           // next 512 B of Es
    if (tid < 128) keys[tid] = 0xFFFFFFFFFFFFFFFFull;
    __syncthreads();
#pragma unroll
    for (int r = 0; r < 4; ++r) {
        unsigned long long key =
            ((unsigned long long)__float_as_uint(best[r]) << 32) | (unsigned)bidx[r];
        atomicMin(&keys[tr * 4 + r], key);
    }
    __syncthreads();

    double lsum = 0.0;
    if (tid < 128) {
        int idx = (int)(keys[tid] & 0xFFFFFFFFull);
        sidx[tid] = idx;
        atomicAdd(&g_hist[idx], 1);
        if (oidx) oidx[n0 + tid] = (float)idx;
        const float* e = emb + idx * DIM;
        float s = 0.f;
#pragma unroll
        for (int d = 0; d < DIM; ++d) {
            float dif = e[d] - Xs[d * 128 + tid];
            s = __fmaf_rn(dif, dif, s);
        }
        lsum = (double)s;
    }
#pragma unroll
    for (int off = 16; off; off >>= 1)
        lsum += __shfl_down_sync(0xffffffffu, lsum, off);
    if (tid < 128 && (tid & 31) == 0) atomicAdd(&g_loss, lsum);
    __syncthreads();

    // quantized_st, NCHW: per channel c, 128 consecutive floats (coalesced)
    for (int i = tid; i < DIM * 128; i += 256) {
        int c = i >> 7, row = i & 127;
        oq[(size_t)img * (DIM * HW) + c * HW + hw0 + row] = emb[sidx[row] * DIM + c];
    }

    // one-hot encodings: 128 rows x 512 float2 (base only 8B-aligned)
    if (oenc) {
        float2* enc2 = (float2*)oenc;
        for (int i = tid; i < 128 * 512; i += 256) {
            int row = i >> 9, jj = i & 511;
            int idx = sidx[row];
            float2 z = make_float2(0.f, 0.f);
            if ((idx >> 1) == jj) ((float*)&z)[idx & 1] = 1.0f;
            enc2[(size_t)(n0 + row) * 512 + jj] = z;
        }
    }
}

// ---------------------------------------------------------------------------
// finalize: loss scalar + perplexity from histogram
// ---------------------------------------------------------------------------
__global__ void finalize_kernel(float* __restrict__ oloss, float* __restrict__ operp) {
    int t = threadIdx.x;                         // 1024 threads
    double p = (double)g_hist[t] / 65536.0;
    double h = -p * log(p + 1e-10);
    __shared__ double sh[32];
#pragma unroll
    for (int off = 16; off; off >>= 1) h += __shfl_down_sync(0xffffffffu, h, off);
    if ((t & 31) == 0) sh[t >> 5] = h;
    __syncthreads();
    if (t < 32) {
        double v = sh[t];
#pragma unroll
        for (int off = 16; off; off >>= 1) v += __shfl_down_sync(0xffffffffu, v, off);
        if (t == 0) {
            operp[0] = (float)exp(v);
            oloss[0] = (float)(1.25 * (g_loss / (double)QELEMS));
        }
    }
}

// ---------------------------------------------------------------------------
extern "C" void kernel_launch(void* const* d_in, const int* in_sizes, int n_in,
                              void* d_out, int out_size) {
    const float* xin = (const float*)d_in[0];
    const float* emb = (const float*)d_in[1];
    if (n_in >= 2 && in_sizes[0] == NCODES * DIM && in_sizes[1] == QELEMS) {
        xin = (const float*)d_in[1];
        emb = (const float*)d_in[0];
    }
    float* out  = (float*)d_out;
    bool   full = (out_size >= FULL_OUT);
    float* o_q   = full ? out + 1 : out;
    float* o_enc = full ? out + (size_t)QELEMS + 2 : nullptr;
    float* o_idx = full ? out + (size_t)QELEMS + 2 + (size_t)NROWS * NCODES : nullptr;

    init_kernel<<<8, 128>>>(emb);
    fused_kernel<<<512, 256>>>(xin, emb, o_q, o_enc, o_idx);
    if (full) finalize_kernel<<<1, 1024>>>(out, out + QELEMS + 1);
}